// round 11
// baseline (speedup 1.0000x reference)
#include <cuda_runtime.h>
#include <math.h>

#define N       1024
#define NN4     (N * N / 4)
#define RESTART 16
#define TPB     256
#define NBLK    512              /* 512 blocks x 256 threads x 2 points = NN4 */
#define NCYC    4

// ---------------- device scratch (allocations forbidden) --------------------
__device__ float4 g_S[16][NN4];       // Chebyshev basis s_0..s_15
__device__ float4 g_x[NN4];
__device__ float  g_part[2][33][NBLK]; // per-cycle parity buffered partials
__device__ volatile unsigned g_flag[NBLK];  // per-block epoch flags
__device__ volatile unsigned g_gen;
__device__ unsigned g_arrive;

// ---------------- sync primitives ----------------------------------------------
__device__ __forceinline__ void gridBarrier() {
    __syncthreads();
    if (threadIdx.x == 0) {
        __threadfence();
        unsigned gen = g_gen;
        if (atomicAdd(&g_arrive, 1u) == (unsigned)(NBLK - 1)) {
            g_arrive = 0u;
            __threadfence();
            g_gen = gen + 1u;
        } else {
            while (g_gen == gen) __nanosleep(64);
        }
        __threadfence();
    }
    __syncthreads();
}

// acquire: wait until both neighbors have published epoch >= tgt
__device__ __forceinline__ void waitNbr(int ln, int rn, unsigned tgt) {
    if (threadIdx.x == 0)  { while (g_flag[ln] < tgt) __nanosleep(32); }
    if (threadIdx.x == 32) { while (g_flag[rn] < tgt) __nanosleep(32); }
    __syncthreads();
    __threadfence();
}

// release: all threads' prior stores visible, then publish epoch
__device__ __forceinline__ void publish(int q, unsigned v) {
    __threadfence();
    __syncthreads();
    if (threadIdx.x == 0) g_flag[q] = v;
}

// ---------------- helpers ----------------------------------------------------
struct Geo {
    int i1, i2;      // f4 indices of the two centers (rows 2q, 2q+1)
    int up, dn;      // f4 indices of rows 2q-1, 2q+2 (periodic)
    int l1, r1, l2, r2;  // scalar wrap indices
};

__device__ __forceinline__ Geo mkgeo() {
    int q   = blockIdx.x;
    int col = threadIdx.x;
    int r1  = q << 1, r2 = r1 + 1;
    Geo o;
    o.i1 = (r1 << 8) | col;
    o.i2 = (r2 << 8) | col;
    o.up = (((r1 - 1) & (N - 1)) << 8) | col;
    o.dn = (((r2 + 1) & (N - 1)) << 8) | col;
    int cl = ((col << 2) - 1) & (N - 1);
    int cr = ((col << 2) + 4) & (N - 1);
    o.l1 = (r1 << 10) | cl;  o.r1 = (r1 << 10) | cr;
    o.l2 = (r2 << 10) | cl;  o.r2 = (r2 << 10) | cr;
    return o;
}

// neighbor-sums for register-resident centers C1,C2 (U/D rows + edges from mem)
__device__ __forceinline__ void nsFromRegs(const float4* __restrict__ u4, const Geo& o,
                                           int lane,
                                           const float4& C1, const float4& C2,
                                           float4& NS1, float4& NS2) {
    float4 U = u4[o.up], D = u4[o.dn];
    float L1 = __shfl_up_sync(0xffffffffu, C1.w, 1);
    float R1 = __shfl_down_sync(0xffffffffu, C1.x, 1);
    float L2 = __shfl_up_sync(0xffffffffu, C2.w, 1);
    float R2 = __shfl_down_sync(0xffffffffu, C2.x, 1);
    if (lane == 0)  { L1 = ((const float*)u4)[o.l1]; L2 = ((const float*)u4)[o.l2]; }
    if (lane == 31) { R1 = ((const float*)u4)[o.r1]; R2 = ((const float*)u4)[o.r2]; }
    NS1.x = L1   + C1.y + U.x  + C2.x;
    NS1.y = C1.x + C1.z + U.y  + C2.y;
    NS1.z = C1.y + C1.w + U.z  + C2.z;
    NS1.w = C1.z + R1   + U.w  + C2.w;
    NS2.x = L2   + C2.y + C1.x + D.x;
    NS2.y = C2.x + C2.z + C1.y + D.y;
    NS2.z = C2.y + C2.w + C1.z + D.z;
    NS2.w = C2.z + R2   + C1.w + D.w;
}

__device__ __forceinline__ void loadF2(const float4* __restrict__ u4, const Geo& o,
                                       int lane,
                                       float4& C1, float4& NS1,
                                       float4& C2, float4& NS2) {
    C1 = u4[o.i1];
    C2 = u4[o.i2];
    nsFromRegs(u4, o, lane, C1, C2, NS1, NS2);
}

__device__ __forceinline__ float dot4(float4 a, float4 b) {
    return a.x * b.x + a.y * b.y + a.z * b.z + a.w * b.w;
}

__device__ __forceinline__ float warpSum(float v) {
#pragma unroll
    for (int o = 16; o > 0; o >>= 1) v += __shfl_down_sync(0xffffffffu, v, o);
    return v;
}

// ---------------- the persistent kernel ----------------------------------------
__global__ void __launch_bounds__(TPB, 4) k_all(const float4* __restrict__ b,
                                                const float4* __restrict__ guess,
                                                float4* __restrict__ out) {
    Geo o = mkgeo();
    int lane = threadIdx.x & 31, warp = threadIdx.x >> 5;
    int q  = blockIdx.x;
    int ln = (q + NBLK - 1) & (NBLK - 1);
    int rn = (q + 1) & (NBLK - 1);
    int t  = threadIdx.x;

    // shared workspace
    __shared__ float  sred[3][TPB / 32];
    __shared__ float  smu[33];
    __shared__ double mu[33];
    __shared__ double M[17][17];
    __shared__ double W[17][16];
    __shared__ double G[16][16], sf[16], rhs[16];
    __shared__ float  cs[16];

    g_x[o.i1] = guess[o.i1];
    g_x[o.i2] = guess[o.i2];
    if (t == 0) g_flag[q] = 0u;
    gridBarrier();

    for (int c = 0; c < NCYC; c++) {
        unsigned base = 17u * (unsigned)c;
        int par = c & 1;

        // ---- residual: s_0 = b - A(x),  A(u) = 4.3u - NS(u) ----
        waitNbr(ln, rn, base);          // neighbors' x of previous cycle
        float4 s1, s2, p1, p2;
        {
            float4 C1, NS1, C2, NS2;
            loadF2(g_x, o, lane, C1, NS1, C2, NS2);
            float4 b1 = b[o.i1], b2v = b[o.i2];
            s1.x = b1.x - (4.3f * C1.x - NS1.x);
            s1.y = b1.y - (4.3f * C1.y - NS1.y);
            s1.z = b1.z - (4.3f * C1.z - NS1.z);
            s1.w = b1.w - (4.3f * C1.w - NS1.w);
            s2.x = b2v.x - (4.3f * C2.x - NS2.x);
            s2.y = b2v.y - (4.3f * C2.y - NS2.y);
            s2.z = b2v.z - (4.3f * C2.z - NS2.z);
            s2.w = b2v.w - (4.3f * C2.w - NS2.w);
            g_S[0][o.i1] = s1;
            g_S[0][o.i2] = s2;
        }
        publish(q, base + 1u);
        p1 = s1; p2 = s2;

        // ---- 16 Chebyshev sweeps, state in registers, neighbor-flag sync ----
        for (int i = 0; i < RESTART; i++) {
            waitNbr(ln, rn, base + 1u + (unsigned)i);   // neighbors' s_i halos

            float4 T1, T2;
            nsFromRegs(g_S[i], o, lane, s1, s2, T1, T2);

            float4 n1, n2;
            if (i == 0) {
                n1.x = -0.25f * T1.x; n1.y = -0.25f * T1.y;
                n1.z = -0.25f * T1.z; n1.w = -0.25f * T1.w;
                n2.x = -0.25f * T2.x; n2.y = -0.25f * T2.y;
                n2.z = -0.25f * T2.z; n2.w = -0.25f * T2.w;
            } else {
                n1.x = -0.5f * T1.x - p1.x; n1.y = -0.5f * T1.y - p1.y;
                n1.z = -0.5f * T1.z - p1.z; n1.w = -0.5f * T1.w - p1.w;
                n2.x = -0.5f * T2.x - p2.x; n2.y = -0.5f * T2.y - p2.y;
                n2.z = -0.5f * T2.z - p2.z; n2.w = -0.5f * T2.w - p2.w;
            }
            if (i < RESTART - 1) {
                g_S[i + 1][o.i1] = n1;
                g_S[i + 1][o.i2] = n2;
                publish(q, base + 2u + (unsigned)i);    // unblock neighbors ASAP
            }

            // dots into per-block partials (no cross-block reduce here)
            float a  = dot4(s1, s1) + dot4(s2, s2);
            float bb = dot4(s1, n1) + dot4(s2, n2);
            float v0 = warpSum(a), v1 = warpSum(bb);
            if (lane == 0) { sred[0][warp] = v0; sred[1][warp] = v1; }
            if (i == RESTART - 1) {
                float a2 = dot4(n1, n1) + dot4(n2, n2);
                float v2 = warpSum(a2);
                if (lane == 0) sred[2][warp] = v2;
            }
            __syncthreads();
            if (t < 2 || (i == RESTART - 1 && t == 2)) {
                float s = 0.f;
#pragma unroll
                for (int w = 0; w < TPB / 32; w++) s += sred[t][w];
                int row = (t == 2) ? 32 : 2 * i + t;
                g_part[par][row][q] = s;
            }
            p1 = s1; p2 = s2;
            s1 = n1; s2 = n2;
        }
        // p = s_15 (registers)

        gridBarrier();   // all partials of this cycle visible everywhere

        // ---- every block: reduce 33 moments + fp64 16x16 solve (redundant) ----
        for (int r = warp; r < 33; r += TPB / 32) {
            float s = 0.f;
            for (int b2 = lane; b2 < NBLK; b2 += 32) s += g_part[par][r][b2];
            s = warpSum(s);
            if (lane == 0) smu[r] = s;
        }
        __syncthreads();
        if (t < 33) {
            double v;
            if (t < 2) v = (double)smu[t];
            else       v = 2.0 * (double)smu[t] - (double)smu[t & 1];
            mu[t] = v;
        }
        __syncthreads();

        for (int idx = t; idx < 289; idx += TPB) {
            int a = idx / 17, b2 = idx % 17;
            int d = a - b2; if (d < 0) d = -d;
            M[a][b2] = 0.5 * (mu[a + b2] + mu[d]);
        }
        __syncthreads();
        for (int idx = t; idx < 272; idx += TPB) {
            int r = idx / 16, b2 = idx % 16;
            double w = 4.3 * M[r][b2];
            w += (b2 == 0) ? 4.0 * M[r][1] : 2.0 * (M[r][b2 + 1] + M[r][b2 - 1]);
            W[r][b2] = w;
        }
        __syncthreads();
        {
            int a = t >> 4, b2 = t & 15;
            double g = 4.3 * W[a][b2];
            g += (a == 0) ? 4.0 * W[1][b2] : 2.0 * (W[a + 1][b2] + W[a - 1][b2]);
            G[a][b2] = g;
        }
        if (t < 16) {
            double r = 4.3 * M[t][0];
            r += (t == 0) ? 4.0 * M[1][0] : 2.0 * (M[t + 1][0] + M[t - 1][0]);
            rhs[t] = r;
        }
        __syncthreads();
        if (t == 0) {
            double tr = 0.0;
            for (int k = 0; k < 16; k++) tr += G[k][k];
            double ridge = 1e-12 + 1e-10 * (tr / 16.0);
            for (int k = 0; k < 16; k++) G[k][k] += ridge;
        }
        __syncthreads();
        for (int p = 0; p < 16; p++) {
            if (t > p && t < 16) sf[t] = G[t][p] / G[p][p];
            __syncthreads();
            int r = t >> 4, cc = t & 15;
            if (r > p && cc > p) G[r][cc] -= sf[r] * G[p][cc];
            if (t > p && t < 16) rhs[t] -= sf[t] * rhs[p];
            __syncthreads();
        }
        if (t == 0) {
            for (int p = 15; p >= 0; p--) {
                double su = rhs[p];
                for (int cc = p + 1; cc < 16; cc++) su -= G[p][cc] * rhs[cc];
                rhs[p] = su / G[p][p];
            }
        }
        __syncthreads();
        if (t < 16) cs[t] = (float)rhs[t];
        __syncthreads();

        // ---- x += sum_k c_k s_k  (s_15 from registers; purely local reads) ----
        {
            float4 x1 = g_x[o.i1], x2 = g_x[o.i2];
#pragma unroll 4
            for (int k = 0; k < RESTART - 1; k++) {
                float y = cs[k];
                float4 v = g_S[k][o.i1];
                x1.x += y * v.x; x1.y += y * v.y; x1.z += y * v.z; x1.w += y * v.w;
                v = g_S[k][o.i2];
                x2.x += y * v.x; x2.y += y * v.y; x2.z += y * v.z; x2.w += y * v.w;
            }
            float y15 = cs[RESTART - 1];
            x1.x += y15 * p1.x; x1.y += y15 * p1.y; x1.z += y15 * p1.z; x1.w += y15 * p1.w;
            x2.x += y15 * p2.x; x2.y += y15 * p2.y; x2.z += y15 * p2.z; x2.w += y15 * p2.w;

            if (c == NCYC - 1) {
                out[o.i1] = x1; out[o.i2] = x2;
            } else {
                g_x[o.i1] = x1; g_x[o.i2] = x2;
                publish(q, base + 17u);     // gates next cycle's residual
            }
        }
    }
}

// ---------------- host orchestration ----------------------------------------
extern "C" void kernel_launch(void* const* d_in, const int* in_sizes, int n_in,
                              void* d_out, int out_size) {
    (void)in_sizes; (void)n_in; (void)out_size;
    const float4* src   = (const float4*)d_in[0];
    const float4* guess = (const float4*)d_in[1];
    float4* out = (float4*)d_out;

    k_all<<<NBLK, TPB>>>(src, guess, out);
}

// round 12
// speedup vs baseline: 2.1217x; 2.1217x over previous
#include <cuda_runtime.h>
#include <math.h>

#define N       1024
#define NN4     (N * N / 4)
#define RESTART 16
#define TPB     256
#define NBLK    512              /* 512 blocks x 256 threads x 2 points = NN4 */
#define NCYC    4

// ---------------- device scratch (allocations forbidden) --------------------
__device__ float4 g_S[16][NN4];    // Chebyshev basis s_0..s_15
__device__ float4 g_x[NN4];
__device__ float  g_part[33][NBLK];
__device__ volatile unsigned g_gen;
__device__ unsigned g_arrive;

// ---------------- grid barrier -------------------------------------------------
__device__ __forceinline__ void gridBarrier() {
    __syncthreads();
    if (threadIdx.x == 0) {
        __threadfence();
        unsigned gen = g_gen;
        if (atomicAdd(&g_arrive, 1u) == (unsigned)(NBLK - 1)) {
            g_arrive = 0u;
            __threadfence();
            g_gen = gen + 1u;
        } else {
            while (g_gen == gen) __nanosleep(64);
        }
        __threadfence();
    }
    __syncthreads();
}

// ---------------- helpers ------------------------------------------------------
__device__ __forceinline__ float4 ns5(float4 C, float L, float R, float4 U, float4 D) {
    float4 n;
    n.x = L   + C.y + U.x + D.x;
    n.y = C.x + C.z + U.y + D.y;
    n.z = C.y + C.w + U.z + D.z;
    n.w = C.z + R   + U.w + D.w;
    return n;
}

// load a row f4 + its lateral scalars (shuffle; edge lanes from memory)
__device__ __forceinline__ float4 loadLat(const float4* __restrict__ u4, int idx,
                                          int li, int ri, int lane,
                                          float& L, float& R) {
    float4 C = u4[idx];
    L = __shfl_up_sync(0xffffffffu, C.w, 1);
    R = __shfl_down_sync(0xffffffffu, C.x, 1);
    if (lane == 0)  L = ((const float*)u4)[li];
    if (lane == 31) R = ((const float*)u4)[ri];
    return C;
}

// laterals for a register-resident row whose values are ALSO in memory u4
__device__ __forceinline__ void latReg(const float4* __restrict__ u4, float4 C,
                                       int li, int ri, int lane,
                                       float& L, float& R) {
    L = __shfl_up_sync(0xffffffffu, C.w, 1);
    R = __shfl_down_sync(0xffffffffu, C.x, 1);
    if (lane == 0)  L = ((const float*)u4)[li];
    if (lane == 31) R = ((const float*)u4)[ri];
}

__device__ __forceinline__ float dot4(float4 a, float4 b) {
    return a.x * b.x + a.y * b.y + a.z * b.z + a.w * b.w;
}

__device__ __forceinline__ float4 sub_half_ns(float4 NS, float4 P) { // -NS/2 - P
    float4 r;
    r.x = -0.5f * NS.x - P.x; r.y = -0.5f * NS.y - P.y;
    r.z = -0.5f * NS.z - P.z; r.w = -0.5f * NS.w - P.w;
    return r;
}

__device__ __forceinline__ float4 quarter_neg(float4 NS) {           // -NS/4
    float4 r;
    r.x = -0.25f * NS.x; r.y = -0.25f * NS.y;
    r.z = -0.25f * NS.z; r.w = -0.25f * NS.w;
    return r;
}

__device__ __forceinline__ float warpSum(float v) {
#pragma unroll
    for (int o = 16; o > 0; o >>= 1) v += __shfl_down_sync(0xffffffffu, v, o);
    return v;
}

// ---------------- the persistent kernel ------------------------------------------
__global__ void __launch_bounds__(TPB, 4) k_all(const float4* __restrict__ b,
                                                const float4* __restrict__ guess,
                                                float4* __restrict__ out) {
    int q = blockIdx.x, t = threadIdx.x;
    int lane = t & 31, warp = t >> 5;
    int col = t;

    // geometry: block owns rows c=2q, d=2q+1
    int rc_ = q << 1, rd_ = rc_ + 1;
    int iC1 = (rc_ << 8) | col,               iC2 = (rd_ << 8) | col;
    int iB  = (((rc_ - 1) & 1023) << 8) | col;
    int iE  = (((rd_ + 1) & 1023) << 8) | col;
    int iA  = (((rc_ - 2) & 1023) << 8) | col;
    int iF  = (((rd_ + 2) & 1023) << 8) | col;
    int cl  = ((col << 2) - 1) & 1023, cr = ((col << 2) + 4) & 1023;
    int lc  = (rc_ << 10) | cl,  rcx = (rc_ << 10) | cr;
    int ldx = (rd_ << 10) | cl,  rdx = (rd_ << 10) | cr;
    int lb  = (((rc_ - 1) & 1023) << 10) | cl, rb = (((rc_ - 1) & 1023) << 10) | cr;
    int le  = (((rd_ + 1) & 1023) << 10) | cl, re = (((rd_ + 1) & 1023) << 10) | cr;

    __shared__ float4 sN1[256], sN2[256];     // s_{i+1} center rows (lateral exch.)
    __shared__ float  sred[5][TPB / 32];
    __shared__ float  smu[33];
    __shared__ double mu[33];
    __shared__ double M[17][17];
    __shared__ double W[17][16];
    __shared__ double G[16][16], sf[16], rhs[16];
    __shared__ float  cs[16];

    g_x[iC1] = guess[iC1];
    g_x[iC2] = guess[iC2];
    gridBarrier();

    for (int c = 0; c < NCYC; c++) {
        // ---- residual: s_0 = b - A(x),  A(u) = 4.3u - NS(u) ----
        float4 s1, s2, p1, p2;
        {
            float Lc, Rc, Ld, Rd;
            float4 Cx1 = loadLat(g_x, iC1, lc, rcx, lane, Lc, Rc);
            float4 Cx2 = loadLat(g_x, iC2, ldx, rdx, lane, Ld, Rd);
            float4 U = g_x[iB], D = g_x[iE];
            float4 NSc = ns5(Cx1, Lc, Rc, U, Cx2);
            float4 NSd = ns5(Cx2, Ld, Rd, Cx1, D);
            float4 b1 = b[iC1], b2v = b[iC2];
            s1.x = b1.x - (4.3f * Cx1.x - NSc.x);
            s1.y = b1.y - (4.3f * Cx1.y - NSc.y);
            s1.z = b1.z - (4.3f * Cx1.z - NSc.z);
            s1.w = b1.w - (4.3f * Cx1.w - NSc.w);
            s2.x = b2v.x - (4.3f * Cx2.x - NSd.x);
            s2.y = b2v.y - (4.3f * Cx2.y - NSd.y);
            s2.z = b2v.z - (4.3f * Cx2.z - NSd.z);
            s2.w = b2v.w - (4.3f * Cx2.w - NSd.w);
            g_S[0][iC1] = s1;
            g_S[0][iC2] = s2;
            p1 = s1; p2 = s2;  // dummy
        }
        gridBarrier();

        // ---- 8 fused Chebyshev double-steps (i = 2j, 2j+1) ----
        for (int j = 0; j < 8; j++) {
            int i = 2 * j;
            const float4* __restrict__ Si = g_S[i];

            // halo rows of s_i
            float Lb, Rb, Le, Re;
            float4 A  = Si[iA];
            float4 Bq = loadLat(Si, iB, lb, rb, lane, Lb, Rb);
            float4 E  = loadLat(Si, iE, le, re, lane, Le, Re);
            float4 F  = Si[iF];
            // center laterals of s_i (values also in memory)
            float Lc, Rc, Ld, Rd;
            latReg(Si, s1, lc, rcx, lane, Lc, Rc);
            latReg(Si, s2, ldx, rdx, lane, Ld, Rd);

            float4 NSb = ns5(Bq, Lb, Rb, A, s1);
            float4 NSe = ns5(E, Le, Re, s2, F);
            float4 NSc = ns5(s1, Lc, Rc, Bq, s2);
            float4 NSd = ns5(s2, Ld, Rd, s1, E);

            float4 nb, ne, n1, n2;
            if (i == 0) {
                nb = quarter_neg(NSb); ne = quarter_neg(NSe);
                n1 = quarter_neg(NSc); n2 = quarter_neg(NSd);
            } else {
                const float4* __restrict__ Sm = g_S[i - 1];
                nb = sub_half_ns(NSb, Sm[iB]);
                ne = sub_half_ns(NSe, Sm[iE]);
                n1 = sub_half_ns(NSc, p1);
                n2 = sub_half_ns(NSd, p2);
            }
            g_S[i + 1][iC1] = n1;
            g_S[i + 1][iC2] = n2;
            sN1[col] = n1;
            sN2[col] = n2;
            __syncthreads();

            int colL = (col + 255) & 255, colR = (col + 1) & 255;
            float Ln1 = sN1[colL].w, Rn1 = sN1[colR].x;
            float Ln2 = sN2[colL].w, Rn2 = sN2[colR].x;
            float4 NSc2 = ns5(n1, Ln1, Rn1, nb, n2);
            float4 NSd2 = ns5(n2, Ln2, Rn2, n1, ne);
            float4 m1 = sub_half_ns(NSc2, s1);
            float4 m2 = sub_half_ns(NSd2, s2);
            if (i < 14) {
                g_S[i + 2][iC1] = m1;
                g_S[i + 2][iC2] = m2;
            }

            // raw dots: a_i, b_i, a_{i+1}, b_{i+1} (+ a_16 on last pair)
            float dA = dot4(s1, s1) + dot4(s2, s2);
            float dB = dot4(s1, n1) + dot4(s2, n2);
            float dC = dot4(n1, n1) + dot4(n2, n2);
            float dD = dot4(n1, m1) + dot4(n2, m2);
            float v;
            v = warpSum(dA); if (lane == 0) sred[0][warp] = v;
            v = warpSum(dB); if (lane == 0) sred[1][warp] = v;
            v = warpSum(dC); if (lane == 0) sred[2][warp] = v;
            v = warpSum(dD); if (lane == 0) sred[3][warp] = v;
            if (j == 7) {
                float dE = dot4(m1, m1) + dot4(m2, m2);
                v = warpSum(dE); if (lane == 0) sred[4][warp] = v;
            }
            __syncthreads();
            if (t < 4 || (j == 7 && t == 4)) {
                float s = 0.f;
#pragma unroll
                for (int w = 0; w < TPB / 32; w++) s += sred[t][w];
                int row = (t == 4) ? 32 : 4 * j + t;
                g_part[row][q] = s;
            }
            p1 = n1; p2 = n2;
            s1 = m1; s2 = m2;
            gridBarrier();   // pair-7 barrier doubles as pre-solve barrier
        }
        // after loop: p = s_15 (registers)

        // ---- every block: reduce 33 moments + fp64 16x16 solve (redundant) ----
        for (int r = warp; r < 33; r += TPB / 32) {
            float s = 0.f;
            for (int b2 = lane; b2 < NBLK; b2 += 32) s += g_part[r][b2];
            s = warpSum(s);
            if (lane == 0) smu[r] = s;
        }
        __syncthreads();
        if (t < 33) {
            double vv;
            if (t < 2) vv = (double)smu[t];
            else       vv = 2.0 * (double)smu[t] - (double)smu[t & 1];
            mu[t] = vv;
        }
        __syncthreads();
        for (int idx = t; idx < 289; idx += TPB) {
            int a = idx / 17, b2 = idx % 17;
            int d = a - b2; if (d < 0) d = -d;
            M[a][b2] = 0.5 * (mu[a + b2] + mu[d]);
        }
        __syncthreads();
        for (int idx = t; idx < 272; idx += TPB) {
            int r = idx / 16, b2 = idx % 16;
            double w = 4.3 * M[r][b2];
            w += (b2 == 0) ? 4.0 * M[r][1] : 2.0 * (M[r][b2 + 1] + M[r][b2 - 1]);
            W[r][b2] = w;
        }
        __syncthreads();
        {
            int a = t >> 4, b2 = t & 15;
            double g = 4.3 * W[a][b2];
            g += (a == 0) ? 4.0 * W[1][b2] : 2.0 * (W[a + 1][b2] + W[a - 1][b2]);
            G[a][b2] = g;
        }
        if (t < 16) {
            double r = 4.3 * M[t][0];
            r += (t == 0) ? 4.0 * M[1][0] : 2.0 * (M[t + 1][0] + M[t - 1][0]);
            rhs[t] = r;
        }
        __syncthreads();
        if (t == 0) {
            double tr = 0.0;
            for (int k = 0; k < 16; k++) tr += G[k][k];
            double ridge = 1e-12 + 1e-10 * (tr / 16.0);
            for (int k = 0; k < 16; k++) G[k][k] += ridge;
        }
        __syncthreads();
        for (int p = 0; p < 16; p++) {
            if (t > p && t < 16) sf[t] = G[t][p] / G[p][p];
            __syncthreads();
            int r = t >> 4, cc = t & 15;
            if (r > p && cc > p) G[r][cc] -= sf[r] * G[p][cc];
            if (t > p && t < 16) rhs[t] -= sf[t] * rhs[p];
            __syncthreads();
        }
        if (t == 0) {
            for (int p = 15; p >= 0; p--) {
                double su = rhs[p];
                for (int cc = p + 1; cc < 16; cc++) su -= G[p][cc] * rhs[cc];
                rhs[p] = su / G[p][p];
            }
        }
        __syncthreads();
        if (t < 16) cs[t] = (float)rhs[t];
        __syncthreads();

        // ---- x += sum_k c_k s_k  (s_15 from registers p; purely local reads) ----
        {
            float4 x1 = g_x[iC1], x2 = g_x[iC2];
#pragma unroll 4
            for (int k = 0; k < RESTART - 1; k++) {
                float y = cs[k];
                float4 vv = g_S[k][iC1];
                x1.x += y * vv.x; x1.y += y * vv.y; x1.z += y * vv.z; x1.w += y * vv.w;
                vv = g_S[k][iC2];
                x2.x += y * vv.x; x2.y += y * vv.y; x2.z += y * vv.z; x2.w += y * vv.w;
            }
            float y15 = cs[RESTART - 1];
            x1.x += y15 * p1.x; x1.y += y15 * p1.y; x1.z += y15 * p1.z; x1.w += y15 * p1.w;
            x2.x += y15 * p2.x; x2.y += y15 * p2.y; x2.z += y15 * p2.z; x2.w += y15 * p2.w;

            if (c == NCYC - 1) {
                out[iC1] = x1; out[iC2] = x2;
            } else {
                g_x[iC1] = x1; g_x[iC2] = x2;
                gridBarrier();
            }
        }
    }
}

// ---------------- host orchestration ----------------------------------------
extern "C" void kernel_launch(void* const* d_in, const int* in_sizes, int n_in,
                              void* d_out, int out_size) {
    (void)in_sizes; (void)n_in; (void)out_size;
    const float4* src   = (const float4*)d_in[0];
    const float4* guess = (const float4*)d_in[1];
    float4* out = (float4*)d_out;

    k_all<<<NBLK, TPB>>>(src, guess, out);
}

// round 13
// speedup vs baseline: 2.2620x; 1.0661x over previous
#include <cuda_runtime.h>
#include <math.h>

#define NN4     (1024 * 1024 / 4)
#define TPB     256
#define NBLK    256              /* 256 blocks x 256 threads x 4 points = NN4 */
#define NCYC    4

// ---------------- device scratch (allocations forbidden) --------------------
__device__ float4 g_S[16][NN4];    // Chebyshev basis s_0..s_15
__device__ float4 g_x[NN4];
__device__ float  g_part[33][NBLK];
__device__ volatile unsigned g_gen;
__device__ unsigned g_arrive;

// ---------------- grid barrier -------------------------------------------------
__device__ __forceinline__ void gridBarrier() {
    __syncthreads();
    if (threadIdx.x == 0) {
        __threadfence();
        unsigned gen = g_gen;
        if (atomicAdd(&g_arrive, 1u) == (unsigned)(NBLK - 1)) {
            g_arrive = 0u;
            __threadfence();
            g_gen = gen + 1u;
        } else {
            while (g_gen == gen) __nanosleep(64);
        }
        __threadfence();
    }
    __syncthreads();
}

// ---------------- helpers ------------------------------------------------------
__device__ __forceinline__ float4 ns5(float4 C, float L, float R, float4 U, float4 D) {
    float4 n;
    n.x = L   + C.y + U.x + D.x;
    n.y = C.x + C.z + U.y + D.y;
    n.z = C.y + C.w + U.z + D.z;
    n.w = C.z + R   + U.w + D.w;
    return n;
}

__device__ __forceinline__ float4 loadLat(const float4* __restrict__ u4, int idx,
                                          int li, int ri, int lane,
                                          float& L, float& R) {
    float4 C = u4[idx];
    L = __shfl_up_sync(0xffffffffu, C.w, 1);
    R = __shfl_down_sync(0xffffffffu, C.x, 1);
    if (lane == 0)  L = ((const float*)u4)[li];
    if (lane == 31) R = ((const float*)u4)[ri];
    return C;
}

// laterals for a register-resident row whose values are ALSO in memory u4
__device__ __forceinline__ void latReg(const float4* __restrict__ u4, float4 C,
                                       int li, int ri, int lane,
                                       float& L, float& R) {
    L = __shfl_up_sync(0xffffffffu, C.w, 1);
    R = __shfl_down_sync(0xffffffffu, C.x, 1);
    if (lane == 0)  L = ((const float*)u4)[li];
    if (lane == 31) R = ((const float*)u4)[ri];
}

__device__ __forceinline__ float dot4(float4 a, float4 b) {
    return a.x * b.x + a.y * b.y + a.z * b.z + a.w * b.w;
}

__device__ __forceinline__ float4 sub_half_ns(float4 NS, float4 P) { // -NS/2 - P
    float4 r;
    r.x = -0.5f * NS.x - P.x; r.y = -0.5f * NS.y - P.y;
    r.z = -0.5f * NS.z - P.z; r.w = -0.5f * NS.w - P.w;
    return r;
}

__device__ __forceinline__ float4 quarter_neg(float4 NS) {           // -NS/4
    float4 r;
    r.x = -0.25f * NS.x; r.y = -0.25f * NS.y;
    r.z = -0.25f * NS.z; r.w = -0.25f * NS.w;
    return r;
}

__device__ __forceinline__ float warpSum(float v) {
#pragma unroll
    for (int o = 16; o > 0; o >>= 1) v += __shfl_down_sync(0xffffffffu, v, o);
    return v;
}

// ---------------- the persistent kernel ------------------------------------------
__global__ void __launch_bounds__(TPB, 2) k_all(const float4* __restrict__ b,
                                                const float4* __restrict__ guess,
                                                float4* __restrict__ out) {
    int q = blockIdx.x, col = threadIdx.x;
    int lane = col & 31, warp = col >> 5, t = col;

    // geometry: block owns 4 rows r0..r0+3, thread owns column col of each
    int r0 = q << 2;
    int cl = ((col << 2) - 1) & 1023, cr = ((col << 2) + 4) & 1023;
    int iC[4], lC[4], rC[4];
#pragma unroll
    for (int k = 0; k < 4; k++) {
        int r = r0 + k;
        iC[k] = (r << 8) | col;
        lC[k] = (r << 10) | cl;
        rC[k] = (r << 10) | cr;
    }
    int rA = (r0 - 2) & 1023, rB = (r0 - 1) & 1023;
    int rE = (r0 + 4) & 1023, rF = (r0 + 5) & 1023;
    int iA = (rA << 8) | col, iB = (rB << 8) | col;
    int iE = (rE << 8) | col, iF = (rF << 8) | col;
    int lB = (rB << 10) | cl, rBx = (rB << 10) | cr;
    int lE = (rE << 10) | cl, rEx = (rE << 10) | cr;

    __shared__ float4 sn[6][TPB];                 // n-level rows for lateral exchange
    __shared__ float  sred[5][TPB / 32];
    __shared__ float  smu[33];
    __shared__ double mu[33];
    __shared__ double M[17][17];
    __shared__ double W[17][16];
    __shared__ double G[16][16], sf[16], rhs[16];
    __shared__ float  cs[16];

    // x register-resident across the whole solve (also mirrored in g_x for halos)
    float4 x[4];
#pragma unroll
    for (int k = 0; k < 4; k++) {
        x[k] = guess[iC[k]];
        g_x[iC[k]] = x[k];
    }
    gridBarrier();

    for (int c = 0; c < NCYC; c++) {
        // ---- residual: s_0 = b - A(x),  A(u) = 4.3u - NS(u) ----
        float4 s[4], p[4];
        {
            float4 XU = g_x[iB], XD = g_x[iE];
            float Lx, Rx;
#pragma unroll
            for (int k = 0; k < 4; k++) {
                latReg(g_x, x[k], lC[k], rC[k], lane, Lx, Rx);
                float4 up = (k == 0) ? XU : x[k - 1];
                float4 dn = (k == 3) ? XD : x[k + 1];
                float4 NS = ns5(x[k], Lx, Rx, up, dn);
                float4 bb = b[iC[k]];
                float4 r;
                r.x = bb.x - (4.3f * x[k].x - NS.x);
                r.y = bb.y - (4.3f * x[k].y - NS.y);
                r.z = bb.z - (4.3f * x[k].z - NS.z);
                r.w = bb.w - (4.3f * x[k].w - NS.w);
                s[k] = r;
                g_S[0][iC[k]] = r;
            }
        }
        gridBarrier();

        // ---- 8 fused Chebyshev double-steps (steps i=2j, 2j+1) ----
        for (int j = 0; j < 8; j++) {
            int i = 2 * j;
            const float4* __restrict__ Si = g_S[i];

            // s_i halo rows (A,B,E,F) + laterals
            float LBv, RBv, LEv, REv;
            float4 A  = Si[iA];
            float4 Bq = loadLat(Si, iB, lB, rBx, lane, LBv, RBv);
            float4 E  = loadLat(Si, iE, lE, rEx, lane, LEv, REv);
            float4 F  = Si[iF];

            // s_{i-1} halo rows (prev term for step-1 halo computation)
            float4 pb, pe;
            if (i > 0) {
                const float4* __restrict__ Sm = g_S[i - 1];
                pb = Sm[iB];
                pe = Sm[iE];
            }

            // step 1: n at rows r0-1 .. r0+4 (nh[0..5])
            float4 nh[6];
            {
                float4 NS = ns5(Bq, LBv, RBv, A, s[0]);
                nh[0] = (i == 0) ? quarter_neg(NS) : sub_half_ns(NS, pb);
#pragma unroll
                for (int k = 0; k < 4; k++) {
                    float Ls, Rs;
                    latReg(Si, s[k], lC[k], rC[k], lane, Ls, Rs);
                    float4 up = (k == 0) ? Bq : s[k - 1];
                    float4 dn = (k == 3) ? E  : s[k + 1];
                    NS = ns5(s[k], Ls, Rs, up, dn);
                    nh[k + 1] = (i == 0) ? quarter_neg(NS) : sub_half_ns(NS, p[k]);
                }
                NS = ns5(E, LEv, REv, s[3], F);
                nh[5] = (i == 0) ? quarter_neg(NS) : sub_half_ns(NS, pe);
            }
#pragma unroll
            for (int k = 0; k < 4; k++) g_S[i + 1][iC[k]] = nh[k + 1];
#pragma unroll
            for (int r = 0; r < 6; r++) sn[r][col] = nh[r];
            __syncthreads();

            // step 2: m on owned rows (laterals of n from shared)
            int colL = (col + 255) & 255, colR = (col + 1) & 255;
            float4 m[4];
#pragma unroll
            for (int k = 0; k < 4; k++) {
                float Ln = sn[k + 1][colL].w;
                float Rn = sn[k + 1][colR].x;
                float4 NS2 = ns5(nh[k + 1], Ln, Rn, nh[k], nh[k + 2]);
                m[k] = sub_half_ns(NS2, s[k]);
            }
            if (i < 14) {
#pragma unroll
                for (int k = 0; k < 4; k++) g_S[i + 2][iC[k]] = m[k];
            }

            // raw dots over owned rows
            float dA = 0.f, dB2 = 0.f, dC = 0.f, dD = 0.f;
#pragma unroll
            for (int k = 0; k < 4; k++) {
                dA  += dot4(s[k], s[k]);
                dB2 += dot4(s[k], nh[k + 1]);
                dC  += dot4(nh[k + 1], nh[k + 1]);
                dD  += dot4(nh[k + 1], m[k]);
            }
            float v;
            v = warpSum(dA);  if (lane == 0) sred[0][warp] = v;
            v = warpSum(dB2); if (lane == 0) sred[1][warp] = v;
            v = warpSum(dC);  if (lane == 0) sred[2][warp] = v;
            v = warpSum(dD);  if (lane == 0) sred[3][warp] = v;
            if (j == 7) {
                float dE = 0.f;
#pragma unroll
                for (int k = 0; k < 4; k++) dE += dot4(m[k], m[k]);
                v = warpSum(dE);
                if (lane == 0) sred[4][warp] = v;
            }
            __syncthreads();
            if (t < 4 || (j == 7 && t == 4)) {
                float sum = 0.f;
#pragma unroll
                for (int w = 0; w < TPB / 32; w++) sum += sred[t][w];
                int row = (t == 4) ? 32 : 4 * j + t;
                g_part[row][q] = sum;
            }
#pragma unroll
            for (int k = 0; k < 4; k++) { p[k] = nh[k + 1]; s[k] = m[k]; }
            gridBarrier();   // j==7 barrier doubles as pre-solve barrier
        }
        // p = s_15 (registers)

        // ---- every block: reduce 33 moments + fp64 16x16 solve (redundant) ----
        for (int r = warp; r < 33; r += TPB / 32) {
            float sum = 0.f;
            for (int b2 = lane; b2 < NBLK; b2 += 32) sum += g_part[r][b2];
            sum = warpSum(sum);
            if (lane == 0) smu[r] = sum;
        }
        __syncthreads();
        if (t < 33) {
            double vv;
            if (t < 2) vv = (double)smu[t];
            else       vv = 2.0 * (double)smu[t] - (double)smu[t & 1];
            mu[t] = vv;
        }
        __syncthreads();
        for (int idx = t; idx < 289; idx += TPB) {
            int a = idx / 17, b2 = idx % 17;
            int d = a - b2; if (d < 0) d = -d;
            M[a][b2] = 0.5 * (mu[a + b2] + mu[d]);
        }
        __syncthreads();
        for (int idx = t; idx < 272; idx += TPB) {
            int r = idx / 16, b2 = idx % 16;
            double w = 4.3 * M[r][b2];
            w += (b2 == 0) ? 4.0 * M[r][1] : 2.0 * (M[r][b2 + 1] + M[r][b2 - 1]);
            W[r][b2] = w;
        }
        __syncthreads();
        {
            int a = t >> 4, b2 = t & 15;
            double g = 4.3 * W[a][b2];
            g += (a == 0) ? 4.0 * W[1][b2] : 2.0 * (W[a + 1][b2] + W[a - 1][b2]);
            G[a][b2] = g;
        }
        if (t < 16) {
            double r = 4.3 * M[t][0];
            r += (t == 0) ? 4.0 * M[1][0] : 2.0 * (M[t + 1][0] + M[t - 1][0]);
            rhs[t] = r;
        }
        __syncthreads();
        if (t == 0) {
            double tr = 0.0;
            for (int k = 0; k < 16; k++) tr += G[k][k];
            double ridge = 1e-12 + 1e-10 * (tr / 16.0);
            for (int k = 0; k < 16; k++) G[k][k] += ridge;
        }
        __syncthreads();
        for (int pp = 0; pp < 16; pp++) {
            if (t > pp && t < 16) sf[t] = G[t][pp] / G[pp][pp];
            __syncthreads();
            int r = t >> 4, cc = t & 15;
            if (r > pp && cc > pp) G[r][cc] -= sf[r] * G[pp][cc];
            if (t > pp && t < 16) rhs[t] -= sf[t] * rhs[pp];
            __syncthreads();
        }
        if (t == 0) {
            for (int pp = 15; pp >= 0; pp--) {
                double su = rhs[pp];
                for (int cc = pp + 1; cc < 16; cc++) su -= G[pp][cc] * rhs[cc];
                rhs[pp] = su / G[pp][pp];
            }
        }
        __syncthreads();
        if (t < 16) cs[t] = (float)rhs[t];
        __syncthreads();

        // ---- x += sum_k c_k s_k  (x and s_15 register-resident) ----
#pragma unroll 2
        for (int kk = 0; kk < 15; kk++) {
            float y = cs[kk];
#pragma unroll
            for (int k = 0; k < 4; k++) {
                float4 vv = g_S[kk][iC[k]];
                x[k].x += y * vv.x; x[k].y += y * vv.y;
                x[k].z += y * vv.z; x[k].w += y * vv.w;
            }
        }
        {
            float y15 = cs[15];
#pragma unroll
            for (int k = 0; k < 4; k++) {
                x[k].x += y15 * p[k].x; x[k].y += y15 * p[k].y;
                x[k].z += y15 * p[k].z; x[k].w += y15 * p[k].w;
            }
        }
        if (c == NCYC - 1) {
#pragma unroll
            for (int k = 0; k < 4; k++) out[iC[k]] = x[k];
        } else {
#pragma unroll
            for (int k = 0; k < 4; k++) g_x[iC[k]] = x[k];
            gridBarrier();
        }
    }
}

// ---------------- host orchestration ----------------------------------------
extern "C" void kernel_launch(void* const* d_in, const int* in_sizes, int n_in,
                              void* d_out, int out_size) {
    (void)in_sizes; (void)n_in; (void)out_size;
    const float4* src   = (const float4*)d_in[0];
    const float4* guess = (const float4*)d_in[1];
    float4* out = (float4*)d_out;

    k_all<<<NBLK, TPB>>>(src, guess, out);
}

// round 14
// speedup vs baseline: 2.3683x; 1.0470x over previous
#include <cuda_runtime.h>
#include <math.h>

#define NN4     (1024 * 1024 / 4)
#define TPB     256
#define NBLK    256              /* 256 blocks x 256 threads x 4 points = NN4 */
#define NCYC    4

// ---------------- device scratch (allocations forbidden) --------------------
__device__ float4 g_S[16][NN4];    // Chebyshev basis s_0..s_15
__device__ float  g_part[33][NBLK];
__device__ volatile unsigned g_gen;
__device__ unsigned g_arrive;

// ---------------- grid barrier (pure spin; 2 blocks/SM co-resident) -----------
__device__ __forceinline__ void gridBarrier() {
    __syncthreads();
    if (threadIdx.x == 0) {
        __threadfence();
        unsigned gen = g_gen;
        if (atomicAdd(&g_arrive, 1u) == (unsigned)(NBLK - 1)) {
            g_arrive = 0u;
            __threadfence();
            g_gen = gen + 1u;
        } else {
            while (g_gen == gen) { }
        }
        __threadfence();
    }
    __syncthreads();
}

// ---------------- helpers ------------------------------------------------------
__device__ __forceinline__ float4 ns5(float4 C, float L, float R, float4 U, float4 D) {
    float4 n;
    n.x = L   + C.y + U.x + D.x;
    n.y = C.x + C.z + U.y + D.y;
    n.z = C.y + C.w + U.z + D.z;
    n.w = C.z + R   + U.w + D.w;
    return n;
}

__device__ __forceinline__ float4 loadLat(const float4* __restrict__ u4, int idx,
                                          int li, int ri, int lane,
                                          float& L, float& R) {
    float4 C = u4[idx];
    L = __shfl_up_sync(0xffffffffu, C.w, 1);
    R = __shfl_down_sync(0xffffffffu, C.x, 1);
    if (lane == 0)  L = ((const float*)u4)[li];
    if (lane == 31) R = ((const float*)u4)[ri];
    return C;
}

// laterals for a register-resident row whose values are ALSO in memory u4
__device__ __forceinline__ void latReg(const float4* __restrict__ u4, float4 C,
                                       int li, int ri, int lane,
                                       float& L, float& R) {
    L = __shfl_up_sync(0xffffffffu, C.w, 1);
    R = __shfl_down_sync(0xffffffffu, C.x, 1);
    if (lane == 0)  L = ((const float*)u4)[li];
    if (lane == 31) R = ((const float*)u4)[ri];
}

__device__ __forceinline__ float dot4(float4 a, float4 b) {
    return a.x * b.x + a.y * b.y + a.z * b.z + a.w * b.w;
}

__device__ __forceinline__ float4 sub_half_ns(float4 NS, float4 P) { // -NS/2 - P
    float4 r;
    r.x = -0.5f * NS.x - P.x; r.y = -0.5f * NS.y - P.y;
    r.z = -0.5f * NS.z - P.z; r.w = -0.5f * NS.w - P.w;
    return r;
}

__device__ __forceinline__ float4 quarter_neg(float4 NS) {           // -NS/4
    float4 r;
    r.x = -0.25f * NS.x; r.y = -0.25f * NS.y;
    r.z = -0.25f * NS.z; r.w = -0.25f * NS.w;
    return r;
}

__device__ __forceinline__ float warpSum(float v) {
#pragma unroll
    for (int o = 16; o > 0; o >>= 1) v += __shfl_down_sync(0xffffffffu, v, o);
    return v;
}

// ---------------- the persistent kernel ------------------------------------------
__global__ void __launch_bounds__(TPB, 2) k_all(const float4* __restrict__ b,
                                                const float4* __restrict__ guess,
                                                float4* __restrict__ out) {
    int q = blockIdx.x, col = threadIdx.x;
    int lane = col & 31, warp = col >> 5, t = col;

    // geometry: block owns 4 rows r0..r0+3, thread owns column col of each
    int r0 = q << 2;
    int cl = ((col << 2) - 1) & 1023, cr = ((col << 2) + 4) & 1023;
    int iC[4], lC[4], rC[4];
#pragma unroll
    for (int k = 0; k < 4; k++) {
        int r = r0 + k;
        iC[k] = (r << 8) | col;
        lC[k] = (r << 10) | cl;
        rC[k] = (r << 10) | cr;
    }
    int rA = (r0 - 2) & 1023, rB = (r0 - 1) & 1023;
    int rE = (r0 + 4) & 1023, rF = (r0 + 5) & 1023;
    int iA = (rA << 8) | col, iB = (rB << 8) | col;
    int iE = (rE << 8) | col, iF = (rF << 8) | col;
    int lB = (rB << 10) | cl, rBx = (rB << 10) | cr;
    int lE = (rE << 10) | cl, rEx = (rE << 10) | cr;

    __shared__ float4 sn[6][TPB];                 // n-level rows for lateral exchange
    __shared__ float  sred[5][TPB / 32];
    __shared__ float  smu[33];
    __shared__ double mu[33];
    __shared__ double M[17][17];
    __shared__ double W[17][16];
    __shared__ double G[16][16], sf[16], rhs[16];
    __shared__ float  cs[16], ds[17];

    // x register-resident across the entire solve (never stored to global)
    float4 x[4];
#pragma unroll
    for (int k = 0; k < 4; k++) x[k] = guess[iC[k]];

    // ---- cycle-0 residual: s_0 = b - A(guess), halos straight from guess ----
    float4 s[4], p[4];
    {
        float4 XU = guess[iB], XD = guess[iE];
        float Lx, Rx;
#pragma unroll
        for (int k = 0; k < 4; k++) {
            latReg(guess, x[k], lC[k], rC[k], lane, Lx, Rx);
            float4 up = (k == 0) ? XU : x[k - 1];
            float4 dn = (k == 3) ? XD : x[k + 1];
            float4 NS = ns5(x[k], Lx, Rx, up, dn);
            float4 bb = b[iC[k]];
            float4 r;
            r.x = bb.x - (4.3f * x[k].x - NS.x);
            r.y = bb.y - (4.3f * x[k].y - NS.y);
            r.z = bb.z - (4.3f * x[k].z - NS.z);
            r.w = bb.w - (4.3f * x[k].w - NS.w);
            s[k] = r;
            g_S[0][iC[k]] = r;
        }
    }
    gridBarrier();

    for (int c = 0; c < NCYC; c++) {
        // ---- 8 fused Chebyshev double-steps; s_{i-1} halos carried in cb/ce ----
        float4 cb, ce;
        for (int j = 0; j < 8; j++) {
            int i = 2 * j;
            const float4* __restrict__ Si = g_S[i];

            // s_i halo rows (A,B,E,F) + laterals
            float LBv, RBv, LEv, REv;
            float4 A  = Si[iA];
            float4 Bq = loadLat(Si, iB, lB, rBx, lane, LBv, RBv);
            float4 E  = loadLat(Si, iE, lE, rEx, lane, LEv, REv);
            float4 F  = Si[iF];

            // step 1: n at rows r0-1 .. r0+4 (nh[0..5]); s_{i-1} halos from carry
            float4 nh[6];
            {
                float4 NS = ns5(Bq, LBv, RBv, A, s[0]);
                nh[0] = (i == 0) ? quarter_neg(NS) : sub_half_ns(NS, cb);
#pragma unroll
                for (int k = 0; k < 4; k++) {
                    float Ls, Rs;
                    latReg(Si, s[k], lC[k], rC[k], lane, Ls, Rs);
                    float4 up = (k == 0) ? Bq : s[k - 1];
                    float4 dn = (k == 3) ? E  : s[k + 1];
                    NS = ns5(s[k], Ls, Rs, up, dn);
                    nh[k + 1] = (i == 0) ? quarter_neg(NS) : sub_half_ns(NS, p[k]);
                }
                NS = ns5(E, LEv, REv, s[3], F);
                nh[5] = (i == 0) ? quarter_neg(NS) : sub_half_ns(NS, ce);
            }
#pragma unroll
            for (int k = 0; k < 4; k++) g_S[i + 1][iC[k]] = nh[k + 1];
#pragma unroll
            for (int r = 0; r < 6; r++) sn[r][col] = nh[r];
            __syncthreads();

            // step 2: m on owned rows (laterals of n from shared)
            int colL = (col + 255) & 255, colR = (col + 1) & 255;
            float4 m[4];
#pragma unroll
            for (int k = 0; k < 4; k++) {
                float Ln = sn[k + 1][colL].w;
                float Rn = sn[k + 1][colR].x;
                float4 NS2 = ns5(nh[k + 1], Ln, Rn, nh[k], nh[k + 2]);
                m[k] = sub_half_ns(NS2, s[k]);
            }
            if (i < 14) {
#pragma unroll
                for (int k = 0; k < 4; k++) g_S[i + 2][iC[k]] = m[k];
            }

            // raw dots over owned rows
            float dA = 0.f, dB2 = 0.f, dC = 0.f, dD = 0.f;
#pragma unroll
            for (int k = 0; k < 4; k++) {
                dA  += dot4(s[k], s[k]);
                dB2 += dot4(s[k], nh[k + 1]);
                dC  += dot4(nh[k + 1], nh[k + 1]);
                dD  += dot4(nh[k + 1], m[k]);
            }
            float v;
            v = warpSum(dA);  if (lane == 0) sred[0][warp] = v;
            v = warpSum(dB2); if (lane == 0) sred[1][warp] = v;
            v = warpSum(dC);  if (lane == 0) sred[2][warp] = v;
            v = warpSum(dD);  if (lane == 0) sred[3][warp] = v;
            if (j == 7) {
                float dE = 0.f;
#pragma unroll
                for (int k = 0; k < 4; k++) dE += dot4(m[k], m[k]);
                v = warpSum(dE);
                if (lane == 0) sred[4][warp] = v;
            }
            __syncthreads();
            if (t < 4 || (j == 7 && t == 4)) {
                float sum = 0.f;
#pragma unroll
                for (int w = 0; w < TPB / 32; w++) sum += sred[t][w];
                int row = (t == 4) ? 32 : 4 * j + t;
                g_part[row][q] = sum;
            }
            cb = nh[0]; ce = nh[5];     // carry s_{i+1} halos -> next pair's s_{i-1}
#pragma unroll
            for (int k = 0; k < 4; k++) { p[k] = nh[k + 1]; s[k] = m[k]; }
            gridBarrier();   // j==7 barrier doubles as pre-solve barrier
        }
        // registers now: p = s_15, s = s_16

        // ---- every block: reduce 33 moments + fp64 16x16 solve (redundant) ----
        for (int r = warp; r < 33; r += TPB / 32) {
            float sum = 0.f;
            for (int b2 = lane; b2 < NBLK; b2 += 32) sum += g_part[r][b2];
            sum = warpSum(sum);
            if (lane == 0) smu[r] = sum;
        }
        __syncthreads();
        if (t < 33) {
            double vv;
            if (t < 2) vv = (double)smu[t];
            else       vv = 2.0 * (double)smu[t] - (double)smu[t & 1];
            mu[t] = vv;
        }
        __syncthreads();
        for (int idx = t; idx < 289; idx += TPB) {
            int a = idx / 17, b2 = idx % 17;
            int d = a - b2; if (d < 0) d = -d;
            M[a][b2] = 0.5 * (mu[a + b2] + mu[d]);
        }
        __syncthreads();
        for (int idx = t; idx < 272; idx += TPB) {
            int r = idx / 16, b2 = idx % 16;
            double w = 4.3 * M[r][b2];
            w += (b2 == 0) ? 4.0 * M[r][1] : 2.0 * (M[r][b2 + 1] + M[r][b2 - 1]);
            W[r][b2] = w;
        }
        __syncthreads();
        {
            int a = t >> 4, b2 = t & 15;
            double g = 4.3 * W[a][b2];
            g += (a == 0) ? 4.0 * W[1][b2] : 2.0 * (W[a + 1][b2] + W[a - 1][b2]);
            G[a][b2] = g;
        }
        if (t < 16) {
            double r = 4.3 * M[t][0];
            r += (t == 0) ? 4.0 * M[1][0] : 2.0 * (M[t + 1][0] + M[t - 1][0]);
            rhs[t] = r;
        }
        __syncthreads();
        if (t == 0) {
            double tr = 0.0;
            for (int k = 0; k < 16; k++) tr += G[k][k];
            double ridge = 1e-12 + 1e-10 * (tr / 16.0);
            for (int k = 0; k < 16; k++) G[k][k] += ridge;
        }
        __syncthreads();
        for (int pp = 0; pp < 16; pp++) {
            if (t > pp && t < 16) sf[t] = G[t][pp] / G[pp][pp];
            __syncthreads();
            int r = t >> 4, cc = t & 15;
            if (r > pp && cc > pp) G[r][cc] -= sf[r] * G[pp][cc];
            if (t > pp && t < 16) rhs[t] -= sf[t] * rhs[pp];
            __syncthreads();
        }
        if (t == 0) {
            for (int pp = 15; pp >= 0; pp--) {
                double su = rhs[pp];
                for (int cc = pp + 1; cc < 16; cc++) su -= G[pp][cc] * rhs[cc];
                rhs[pp] = su / G[pp][pp];
            }
        }
        __syncthreads();
        if (t < 16) cs[t] = (float)rhs[t];
        // d = T c (coefficients of A s_k expansion; includes s_16 term)
        if (t < 17) {
            double dv;
            if (t == 0)       dv = 4.3 * rhs[0] + 2.0 * rhs[1];
            else if (t == 1)  dv = 4.3 * rhs[1] + 4.0 * rhs[0] + 2.0 * rhs[2];
            else if (t <= 14) dv = 4.3 * rhs[t] + 2.0 * rhs[t - 1] + 2.0 * rhs[t + 1];
            else if (t == 15) dv = 4.3 * rhs[15] + 2.0 * rhs[14];
            else              dv = 2.0 * rhs[15];
            ds[t] = (float)dv;
        }
        __syncthreads();

        if (c == NCYC - 1) {
            // ---- final: x += sum c_k s_k, emit ----
#pragma unroll 2
            for (int kk = 0; kk < 15; kk++) {
                float y = cs[kk];
#pragma unroll
                for (int k = 0; k < 4; k++) {
                    float4 vv = g_S[kk][iC[k]];
                    x[k].x += y * vv.x; x[k].y += y * vv.y;
                    x[k].z += y * vv.z; x[k].w += y * vv.w;
                }
            }
            float y15 = cs[15];
#pragma unroll
            for (int k = 0; k < 4; k++) {
                x[k].x += y15 * p[k].x; x[k].y += y15 * p[k].y;
                x[k].z += y15 * p[k].z; x[k].w += y15 * p[k].w;
                out[iC[k]] = x[k];
            }
        } else {
            // ---- fused x update + analytic residual:
            //   x_new = x + sum_{k<=15} c_k s_k
            //   r_new = s_0 - sum_{j<=16} d_j s_j   (s_15=p, s_16=s registers)
            float4 racc[4];
#pragma unroll
            for (int k = 0; k < 4; k++) { racc[k].x = racc[k].y = racc[k].z = racc[k].w = 0.f; }
#pragma unroll 2
            for (int kk = 0; kk < 15; kk++) {
                float y = cs[kk];
                float e = (kk == 0) ? (1.0f - ds[0]) : -ds[kk];
#pragma unroll
                for (int k = 0; k < 4; k++) {
                    float4 vv = g_S[kk][iC[k]];
                    x[k].x += y * vv.x;    x[k].y += y * vv.y;
                    x[k].z += y * vv.z;    x[k].w += y * vv.w;
                    racc[k].x += e * vv.x; racc[k].y += e * vv.y;
                    racc[k].z += e * vv.z; racc[k].w += e * vv.w;
                }
            }
            float y15 = cs[15], d15 = ds[15], d16 = ds[16];
#pragma unroll
            for (int k = 0; k < 4; k++) {
                x[k].x += y15 * p[k].x;  x[k].y += y15 * p[k].y;
                x[k].z += y15 * p[k].z;  x[k].w += y15 * p[k].w;
                racc[k].x -= d15 * p[k].x + d16 * s[k].x;
                racc[k].y -= d15 * p[k].y + d16 * s[k].y;
                racc[k].z -= d15 * p[k].z + d16 * s[k].z;
                racc[k].w -= d15 * p[k].w + d16 * s[k].w;
                s[k] = racc[k];
                g_S[0][iC[k]] = racc[k];
            }
            gridBarrier();
        }
    }
}

// ---------------- host orchestration ----------------------------------------
extern "C" void kernel_launch(void* const* d_in, const int* in_sizes, int n_in,
                              void* d_out, int out_size) {
    (void)in_sizes; (void)n_in; (void)out_size;
    const float4* src   = (const float4*)d_in[0];
    const float4* guess = (const float4*)d_in[1];
    float4* out = (float4*)d_out;

    k_all<<<NBLK, TPB>>>(src, guess, out);
}

// round 15
// speedup vs baseline: 2.4721x; 1.0438x over previous
#include <cuda_runtime.h>
#include <math.h>

#define NN4     (1024 * 1024 / 4)
#define TPB     256
#define NBLK    256              /* 256 blocks x 256 threads x 4 rows = grid */
#define NCYC    4

// ---------------- device scratch (allocations forbidden) --------------------
__device__ float4 g_S[16][NN4];    // Chebyshev basis s_0..s_15
__device__ float  g_part[33][NBLK];
__device__ volatile unsigned g_gen;
__device__ unsigned g_arrive;

// ---------------- grid barrier (pure spin; 2 blocks/SM co-resident) -----------
__device__ __forceinline__ void gridBarrier() {
    __syncthreads();
    if (threadIdx.x == 0) {
        __threadfence();
        unsigned gen = g_gen;
        if (atomicAdd(&g_arrive, 1u) == (unsigned)(NBLK - 1)) {
            g_arrive = 0u;
            __threadfence();
            g_gen = gen + 1u;
        } else {
            while (g_gen == gen) { }
        }
        __threadfence();
    }
    __syncthreads();
}

// ---------------- helpers ------------------------------------------------------
__device__ __forceinline__ float4 ns5(float4 C, float L, float R, float4 U, float4 D) {
    float4 n;
    n.x = L   + C.y + U.x + D.x;
    n.y = C.x + C.z + U.y + D.y;
    n.z = C.y + C.w + U.z + D.z;
    n.w = C.z + R   + U.w + D.w;
    return n;
}

// laterals for a row whose values exist in global u4 (shfl + edge-lane loads)
__device__ __forceinline__ void latG(const float4* __restrict__ u4, float4 C,
                                     int li, int ri, int lane, float& L, float& R) {
    L = __shfl_up_sync(0xffffffffu, C.w, 1);
    R = __shfl_down_sync(0xffffffffu, C.x, 1);
    if (lane == 0)  L = ((const float*)u4)[li];
    if (lane == 31) R = ((const float*)u4)[ri];
}

__device__ __forceinline__ float dot4(float4 a, float4 b) {
    return a.x * b.x + a.y * b.y + a.z * b.z + a.w * b.w;
}

__device__ __forceinline__ float4 sub_half_ns(float4 NS, float4 P) { // -NS/2 - P
    float4 r;
    r.x = -0.5f * NS.x - P.x; r.y = -0.5f * NS.y - P.y;
    r.z = -0.5f * NS.z - P.z; r.w = -0.5f * NS.w - P.w;
    return r;
}

__device__ __forceinline__ float4 quarter_neg(float4 NS) {           // -NS/4
    float4 r;
    r.x = -0.25f * NS.x; r.y = -0.25f * NS.y;
    r.z = -0.25f * NS.z; r.w = -0.25f * NS.w;
    return r;
}

__device__ __forceinline__ float warpSum(float v) {
#pragma unroll
    for (int o = 16; o > 0; o >>= 1) v += __shfl_down_sync(0xffffffffu, v, o);
    return v;
}

// ---------------- the persistent kernel ------------------------------------------
__global__ void __launch_bounds__(TPB, 2) k_all(const float4* __restrict__ b,
                                                const float4* __restrict__ guess,
                                                float4* __restrict__ out) {
    int q = blockIdx.x, col = threadIdx.x;
    int lane = col & 31, warp = col >> 5, t = col;
    int r0 = q << 2;
    int cl = ((col << 2) - 1) & 1023, cr = ((col << 2) + 4) & 1023;

    auto RO = [&](int d) { return (r0 + d) & 1023; };
    auto I4 = [&](int d) { return (RO(d) << 8) | col; };
    auto LI = [&](int d) { return (RO(d) << 10) | cl; };
    auto RI = [&](int d) { return (RO(d) << 10) | cr; };

    __shared__ float4 xb[8][TPB];                 // lateral-exchange buffer
    __shared__ float  sred[9][TPB / 32];
    __shared__ float  smu[33];
    __shared__ double mu[33];
    __shared__ double M[17][17];
    __shared__ double W[17][16];
    __shared__ double G[16][16], sf[16], rhs[16];
    __shared__ float  cs[16], ds[17];

    // x register-resident (cold; ptxas may spill - touched once per cycle)
    float4 x[4];
#pragma unroll
    for (int k = 0; k < 4; k++) x[k] = guess[I4(k)];

    // ---- cycle-0 residual: s_0 = b - A(guess) ----
    float4 s[4], p[4];
    {
        float4 XU = guess[I4(-1)], XD = guess[I4(4)];
        float Lx, Rx;
#pragma unroll
        for (int k = 0; k < 4; k++) {
            latG(guess, x[k], LI(k), RI(k), lane, Lx, Rx);
            float4 up = (k == 0) ? XU : x[k - 1];
            float4 dn = (k == 3) ? XD : x[k + 1];
            float4 NS = ns5(x[k], Lx, Rx, up, dn);
            float4 bb = b[I4(k)];
            float4 r;
            r.x = bb.x - (4.3f * x[k].x - NS.x);
            r.y = bb.y - (4.3f * x[k].y - NS.y);
            r.z = bb.z - (4.3f * x[k].z - NS.z);
            r.w = bb.w - (4.3f * x[k].w - NS.w);
            s[k] = r;
            g_S[0][I4(k)] = r;
        }
    }
    gridBarrier();

    for (int c = 0; c < NCYC; c++) {
        // ---- 4 quad-steps: each computes s_{i+1..i+4} under ONE barrier ----
        for (int jj = 0; jj < 4; jj++) {
            int i = 4 * jj;
            const float4* __restrict__ Si = g_S[i];

            // s_i rows d=-4..7 : owned from regs, halo from global
            float4 S[12];
#pragma unroll
            for (int k = 0; k < 4; k++) S[k + 4] = s[k];
            S[0]  = Si[I4(-4)]; S[1]  = Si[I4(-3)];
            S[2]  = Si[I4(-2)]; S[3]  = Si[I4(-1)];
            S[8]  = Si[I4(4)];  S[9]  = Si[I4(5)];
            S[10] = Si[I4(6)];  S[11] = Si[I4(7)];

            // s_{i-1} rows d=-3..6 (PL); L1 computed in place
            float4 PL[10];
            if (i > 0) {
                const float4* __restrict__ Sm = g_S[i - 1];
#pragma unroll
                for (int k = 0; k < 4; k++) PL[k + 3] = p[k];
                PL[0] = Sm[I4(-3)]; PL[1] = Sm[I4(-2)]; PL[2] = Sm[I4(-1)];
                PL[7] = Sm[I4(4)];  PL[8] = Sm[I4(5)];  PL[9] = Sm[I4(6)];
            }

            // ---- level 1: s_{i+1} rows d=-3..6 ----
#pragma unroll
            for (int d = -3; d <= 6; d++) {
                float L, R;
                latG(Si, S[d + 4], LI(d), RI(d), lane, L, R);
                float4 NS = ns5(S[d + 4], L, R, S[d + 3], S[d + 5]);
                PL[d + 3] = (i == 0) ? quarter_neg(NS) : sub_half_ns(NS, PL[d + 3]);
            }
            float aI = 0.f, bI = 0.f;
#pragma unroll
            for (int k = 0; k < 4; k++) {
                aI += dot4(S[k + 4], S[k + 4]);
                bI += dot4(S[k + 4], PL[k + 3]);
            }
#pragma unroll
            for (int k = 0; k < 4; k++) g_S[i + 1][I4(k)] = PL[k + 3];

            // exchange L1 rows d=-2..5
#pragma unroll
            for (int d = -2; d <= 5; d++) xb[d + 2][col] = PL[d + 3];
            __syncthreads();
            int colL = (col + 255) & 255, colR = (col + 1) & 255;

            // ---- level 2: s_{i+2} rows d=-2..5 ----
            float4 L2a[8];
#pragma unroll
            for (int d = -2; d <= 5; d++) {
                float L = xb[d + 2][colL].w;
                float R = xb[d + 2][colR].x;
                float4 NS = ns5(PL[d + 3], L, R, PL[d + 2], PL[d + 4]);
                L2a[d + 2] = sub_half_ns(NS, S[d + 4]);
            }
            float aI1 = 0.f, bI1 = 0.f;
#pragma unroll
            for (int k = 0; k < 4; k++) {
                aI1 += dot4(PL[k + 3], PL[k + 3]);
                bI1 += dot4(PL[k + 3], L2a[k + 2]);
            }
#pragma unroll
            for (int k = 0; k < 4; k++) g_S[i + 2][I4(k)] = L2a[k + 2];

            __syncthreads();
#pragma unroll
            for (int d = -1; d <= 4; d++) xb[d + 1][col] = L2a[d + 2];
            __syncthreads();

            // ---- level 3: s_{i+3} rows d=-1..4 ----
            float4 L3a[6];
#pragma unroll
            for (int d = -1; d <= 4; d++) {
                float L = xb[d + 1][colL].w;
                float R = xb[d + 1][colR].x;
                float4 NS = ns5(L2a[d + 2], L, R, L2a[d + 1], L2a[d + 3]);
                L3a[d + 1] = sub_half_ns(NS, PL[d + 3]);
            }
            float aI2 = 0.f, bI2 = 0.f;
#pragma unroll
            for (int k = 0; k < 4; k++) {
                aI2 += dot4(L2a[k + 2], L2a[k + 2]);
                bI2 += dot4(L2a[k + 2], L3a[k + 1]);
            }
#pragma unroll
            for (int k = 0; k < 4; k++) g_S[i + 3][I4(k)] = L3a[k + 1];

            __syncthreads();
#pragma unroll
            for (int d = 0; d <= 3; d++) xb[d][col] = L3a[d + 1];
            __syncthreads();

            // ---- level 4: s_{i+4} rows d=0..3 ----
            float4 L4a[4];
#pragma unroll
            for (int d = 0; d <= 3; d++) {
                float L = xb[d][colL].w;
                float R = xb[d][colR].x;
                float4 NS = ns5(L3a[d + 1], L, R, L3a[d], L3a[d + 2]);
                L4a[d] = sub_half_ns(NS, L2a[d + 2]);
            }
            float aI3 = 0.f, bI3 = 0.f, a16 = 0.f;
#pragma unroll
            for (int k = 0; k < 4; k++) {
                aI3 += dot4(L3a[k + 1], L3a[k + 1]);
                bI3 += dot4(L3a[k + 1], L4a[k]);
            }
            if (jj == 3) {
#pragma unroll
                for (int k = 0; k < 4; k++) a16 += dot4(L4a[k], L4a[k]);
            } else {
#pragma unroll
                for (int k = 0; k < 4; k++) g_S[i + 4][I4(k)] = L4a[k];
            }

            // ---- reductions: 8 (+1) partial rows ----
            float v;
            v = warpSum(aI);  if (lane == 0) sred[0][warp] = v;
            v = warpSum(bI);  if (lane == 0) sred[1][warp] = v;
            v = warpSum(aI1); if (lane == 0) sred[2][warp] = v;
            v = warpSum(bI1); if (lane == 0) sred[3][warp] = v;
            v = warpSum(aI2); if (lane == 0) sred[4][warp] = v;
            v = warpSum(bI2); if (lane == 0) sred[5][warp] = v;
            v = warpSum(aI3); if (lane == 0) sred[6][warp] = v;
            v = warpSum(bI3); if (lane == 0) sred[7][warp] = v;
            if (jj == 3) {
                v = warpSum(a16);
                if (lane == 0) sred[8][warp] = v;
            }
            __syncthreads();
            if (t < 8 || (jj == 3 && t == 8)) {
                float sum = 0.f;
#pragma unroll
                for (int w = 0; w < TPB / 32; w++) sum += sred[t][w];
                int row = (t == 8) ? 32 : 8 * jj + t;
                g_part[row][q] = sum;
            }
#pragma unroll
            for (int k = 0; k < 4; k++) { p[k] = L3a[k + 1]; s[k] = L4a[k]; }
            gridBarrier();   // jj==3 barrier doubles as pre-solve barrier
        }
        // registers now: p = s_15, s = s_16

        // ---- every block: reduce 33 moments + fp64 16x16 solve (redundant) ----
        for (int r = warp; r < 33; r += TPB / 32) {
            float sum = 0.f;
            for (int b2 = lane; b2 < NBLK; b2 += 32) sum += g_part[r][b2];
            sum = warpSum(sum);
            if (lane == 0) smu[r] = sum;
        }
        __syncthreads();
        if (t < 33) {
            double vv;
            if (t < 2) vv = (double)smu[t];
            else       vv = 2.0 * (double)smu[t] - (double)smu[t & 1];
            mu[t] = vv;
        }
        __syncthreads();
        for (int idx = t; idx < 289; idx += TPB) {
            int a = idx / 17, b2 = idx % 17;
            int d = a - b2; if (d < 0) d = -d;
            M[a][b2] = 0.5 * (mu[a + b2] + mu[d]);
        }
        __syncthreads();
        for (int idx = t; idx < 272; idx += TPB) {
            int r = idx / 16, b2 = idx % 16;
            double w = 4.3 * M[r][b2];
            w += (b2 == 0) ? 4.0 * M[r][1] : 2.0 * (M[r][b2 + 1] + M[r][b2 - 1]);
            W[r][b2] = w;
        }
        __syncthreads();
        {
            int a = t >> 4, b2 = t & 15;
            double g = 4.3 * W[a][b2];
            g += (a == 0) ? 4.0 * W[1][b2] : 2.0 * (W[a + 1][b2] + W[a - 1][b2]);
            G[a][b2] = g;
        }
        if (t < 16) {
            double r = 4.3 * M[t][0];
            r += (t == 0) ? 4.0 * M[1][0] : 2.0 * (M[t + 1][0] + M[t - 1][0]);
            rhs[t] = r;
        }
        __syncthreads();
        if (t == 0) {
            double tr = 0.0;
            for (int k = 0; k < 16; k++) tr += G[k][k];
            double ridge = 1e-12 + 1e-10 * (tr / 16.0);
            for (int k = 0; k < 16; k++) G[k][k] += ridge;
        }
        __syncthreads();
        for (int pp = 0; pp < 16; pp++) {
            if (t > pp && t < 16) sf[t] = G[t][pp] / G[pp][pp];
            __syncthreads();
            int r = t >> 4, cc = t & 15;
            if (r > pp && cc > pp) G[r][cc] -= sf[r] * G[pp][cc];
            if (t > pp && t < 16) rhs[t] -= sf[t] * rhs[pp];
            __syncthreads();
        }
        if (t == 0) {
            for (int pp = 15; pp >= 0; pp--) {
                double su = rhs[pp];
                for (int cc = pp + 1; cc < 16; cc++) su -= G[pp][cc] * rhs[cc];
                rhs[pp] = su / G[pp][pp];
            }
        }
        __syncthreads();
        if (t < 16) cs[t] = (float)rhs[t];
        if (t < 17) {
            double dv;
            if (t == 0)       dv = 4.3 * rhs[0] + 2.0 * rhs[1];
            else if (t == 1)  dv = 4.3 * rhs[1] + 4.0 * rhs[0] + 2.0 * rhs[2];
            else if (t <= 14) dv = 4.3 * rhs[t] + 2.0 * rhs[t - 1] + 2.0 * rhs[t + 1];
            else if (t == 15) dv = 4.3 * rhs[15] + 2.0 * rhs[14];
            else              dv = 2.0 * rhs[15];
            ds[t] = (float)dv;
        }
        __syncthreads();

        if (c == NCYC - 1) {
            // ---- final: x += sum c_k s_k, emit ----
#pragma unroll 2
            for (int kk = 0; kk < 15; kk++) {
                float y = cs[kk];
#pragma unroll
                for (int k = 0; k < 4; k++) {
                    float4 vv = g_S[kk][I4(k)];
                    x[k].x += y * vv.x; x[k].y += y * vv.y;
                    x[k].z += y * vv.z; x[k].w += y * vv.w;
                }
            }
            float y15 = cs[15];
#pragma unroll
            for (int k = 0; k < 4; k++) {
                x[k].x += y15 * p[k].x; x[k].y += y15 * p[k].y;
                x[k].z += y15 * p[k].z; x[k].w += y15 * p[k].w;
                out[I4(k)] = x[k];
            }
        } else {
            // ---- fused x update + analytic residual ----
            float4 racc[4];
#pragma unroll
            for (int k = 0; k < 4; k++) { racc[k].x = racc[k].y = racc[k].z = racc[k].w = 0.f; }
#pragma unroll 2
            for (int kk = 0; kk < 15; kk++) {
                float y = cs[kk];
                float e = (kk == 0) ? (1.0f - ds[0]) : -ds[kk];
#pragma unroll
                for (int k = 0; k < 4; k++) {
                    float4 vv = g_S[kk][I4(k)];
                    x[k].x += y * vv.x;    x[k].y += y * vv.y;
                    x[k].z += y * vv.z;    x[k].w += y * vv.w;
                    racc[k].x += e * vv.x; racc[k].y += e * vv.y;
                    racc[k].z += e * vv.z; racc[k].w += e * vv.w;
                }
            }
            float y15 = cs[15], d15 = ds[15], d16 = ds[16];
#pragma unroll
            for (int k = 0; k < 4; k++) {
                x[k].x += y15 * p[k].x;  x[k].y += y15 * p[k].y;
                x[k].z += y15 * p[k].z;  x[k].w += y15 * p[k].w;
                racc[k].x -= d15 * p[k].x + d16 * s[k].x;
                racc[k].y -= d15 * p[k].y + d16 * s[k].y;
                racc[k].z -= d15 * p[k].z + d16 * s[k].z;
                racc[k].w -= d15 * p[k].w + d16 * s[k].w;
                s[k] = racc[k];
                g_S[0][I4(k)] = racc[k];
            }
            gridBarrier();
        }
    }
}

// ---------------- host orchestration ----------------------------------------
extern "C" void kernel_launch(void* const* d_in, const int* in_sizes, int n_in,
                              void* d_out, int out_size) {
    (void)in_sizes; (void)n_in; (void)out_size;
    const float4* src   = (const float4*)d_in[0];
    const float4* guess = (const float4*)d_in[1];
    float4* out = (float4*)d_out;

    k_all<<<NBLK, TPB>>>(src, guess, out);
}